// round 17
// baseline (speedup 1.0000x reference)
#include <cuda_runtime.h>
#include <cuda_fp16.h>

// DistMult edge score: out[e] = sum_d node[src[e]][d] * rel[e][d] * node[dst[e]][d]
// N_NODES=100000, N_EDGES=600000, DIM=128, int32 indices.
//
// R16 insight: no unit saturated (DRAM 78%, L2 51%, issue 54%, fma+alu 51%)
// -> issue/latency coupled, and compute issue-slots are heavy (8 cvts +
// 12 mults + 20 SHFLs per warp-task). R17 cuts issue work:
//   1. h*t in fp16 (HMUL2): 2 ops for 4 products, then 1 cvt pass + 4 FFMA.
//      rel_err 2.9e-4 -> ~3.6e-4 (threshold 1e-3).
//   2. merge-reduction: 4 accs reduced in 6 SHFLs (was 20); results land in
//      lanes 0/8/16/24 -> edges 0/2/1/3.
// Everything else = R13 (measured-best shape, fp16 node scratch).

#define DIM       128
#define DIM4      32
#define EPW       4
#define MAX_NODES 100000

__device__ __half g_node16[(size_t)MAX_NODES * DIM];   // 25.6 MB scratch

// ---- Kernel 1: fp32 node table -> fp16 scratch ----
__global__ __launch_bounds__(256)
void convert_kernel(const float* __restrict__ node_emb, int total4) {
    int i = blockIdx.x * blockDim.x + threadIdx.x;
    if (i >= total4) return;
    float4 v = reinterpret_cast<const float4*>(node_emb)[i];
    __half2 a = __floats2half2_rn(v.x, v.y);
    __half2 b = __floats2half2_rn(v.z, v.w);
    uint2 o;
    o.x = *reinterpret_cast<unsigned int*>(&a);
    o.y = *reinterpret_cast<unsigned int*>(&b);
    reinterpret_cast<uint2*>(g_node16)[i] = o;
}

// ---- Kernel 2: scorer ----
__global__ __launch_bounds__(256)
void distmult_kernel(const float* __restrict__ rel_emb,
                     const int* __restrict__ src,
                     const int* __restrict__ dst,
                     float* __restrict__ out,
                     int n_edges,
                     int n_nodes) {
    int warp  = (blockIdx.x * blockDim.x + threadIdx.x) >> 5;
    int lane  = threadIdx.x & 31;
    int ebase = warp * EPW;
    if (ebase >= n_edges) return;

    const uint2*  __restrict__ node16 = reinterpret_cast<const uint2*>(g_node16);
    const float4* __restrict__ rel4   = reinterpret_cast<const float4*>(rel_emb);
    int nmax = min(n_nodes, MAX_NODES) - 1;

    // Index loads (warp-uniform broadcast).
    int s[EPW], d[EPW];
    #pragma unroll
    for (int i = 0; i < EPW; i++) {
        int e = ebase + i;
        if (e >= n_edges) e = n_edges - 1;     // 600000 % 4 == 0 anyway
        s[i] = min(max(src[e], 0), nmax);
        d[i] = min(max(dst[e], 0), nmax);
    }

    // Front-batched loads. Lane l owns dims [4l, 4l+4).
    uint2  hq[EPW], tq[EPW];
    float4 rv[EPW];
    #pragma unroll
    for (int i = 0; i < EPW; i++) {
        hq[i] = node16[(unsigned)s[i] * DIM4 + lane];
        tq[i] = node16[(unsigned)d[i] * DIM4 + lane];
        rv[i] = __ldcs(rel4 + (unsigned)(ebase + i) * DIM4 + lane);
    }

    // h*t in fp16 (HMUL2), single convert pass, 4 FFMA per edge.
    float acc[EPW];
    #pragma unroll
    for (int i = 0; i < EPW; i++) {
        __half2 h01 = *reinterpret_cast<__half2*>(&hq[i].x);
        __half2 h23 = *reinterpret_cast<__half2*>(&hq[i].y);
        __half2 t01 = *reinterpret_cast<__half2*>(&tq[i].x);
        __half2 t23 = *reinterpret_cast<__half2*>(&tq[i].y);
        float2 pA = __half22float2(__hmul2(h01, t01));
        float2 pB = __half22float2(__hmul2(h23, t23));
        acc[i] = pA.x * rv[i].x + pA.y * rv[i].y
               + pB.x * rv[i].z + pB.y * rv[i].w;
    }

    // Merge-reduction: 6 SHFLs total for 4 values.
    // Step 1 (xor16): lanes<16 carry acc0/acc2 series, lanes>=16 acc1/acc3.
    bool lo = lane < 16;
    float a  = lo ? acc[0] : acc[1];
    float b  = lo ? acc[1] : acc[0];
    float v01 = a + __shfl_xor_sync(0xffffffffu, b, 16);
    float c  = lo ? acc[2] : acc[3];
    float dd = lo ? acc[3] : acc[2];
    float v23 = c + __shfl_xor_sync(0xffffffffu, dd, 16);

    // Step 2 (xor8): interleave v01/v23 across bit-3 halves.
    bool q = (lane & 8) == 0;
    float x = q ? v01 : v23;
    float y = q ? v23 : v01;
    float w = x + __shfl_xor_sync(0xffffffffu, y, 8);

    // Tree within each 8-lane group.
    w += __shfl_xor_sync(0xffffffffu, w, 4);
    w += __shfl_xor_sync(0xffffffffu, w, 2);
    w += __shfl_xor_sync(0xffffffffu, w, 1);

    // lane 0 -> edge0, lane 8 -> edge2, lane 16 -> edge1, lane 24 -> edge3.
    if ((lane & 7) == 0) {
        int sel  = lane >> 3;                       // 0,1,2,3
        int emap = (sel == 0) ? 0 : (sel == 1) ? 2 : (sel == 2) ? 1 : 3;
        int e = ebase + emap;
        if (e < n_edges)
            out[e] = w;
    }
}

extern "C" void kernel_launch(void* const* d_in, const int* in_sizes, int n_in,
                              void* d_out, int out_size) {
    const float* node_emb = (const float*)d_in[0];
    const float* rel_emb  = (const float*)d_in[1];
    const int*   src      = (const int*)d_in[2];
    const int*   dst      = (const int*)d_in[3];
    float* out = (float*)d_out;

    int n_edges = in_sizes[1] / DIM;
    int n_nodes = in_sizes[0] / DIM;
    int n_conv  = min(n_nodes, MAX_NODES);

    int total4 = n_conv * DIM4;                       // 16B groups to convert
    convert_kernel<<<(total4 + 255) / 256, 256>>>(node_emb, total4);

    int threads = 256;
    int edges_per_block = (threads / 32) * EPW;       // 32
    int blocks = (n_edges + edges_per_block - 1) / edges_per_block;
    distmult_kernel<<<blocks, threads>>>(rel_emb, src, dst, out,
                                         n_edges, n_nodes);
}